// round 2
// baseline (speedup 1.0000x reference)
#include <cuda_runtime.h>
#include <cfloat>
#include <math.h>

#define NPIL 30000
#define MPTS 32
#define NMTOT (30000.0 * 32.0)

// ---------------- scratch (device globals; no allocation) ----------------
__device__ float  g_w[NPIL * MPTS];     // per-point attention weight w_i = max_attn_i / sum
__device__ float4 g_pmean[NPIL];        // per-pillar xyz mean (sum over all 32 / num_points)
__device__ float2 g_wmm[NPIL];          // (max, min) of w over MASKED lanes (i >= m)
__device__ double g_mom[65];            // global BN sufficient statistics
__device__ float  g_As[64 * 4];         // A_c * s_c   (xyz,I coefficients, BN-scale folded)
__device__ float  g_Gs[64 * 6];         // G_c * s_c   (pillar-constant coefficients)
__device__ float  g_t[64];              // BN bias t_c = beta - mean*s

__global__ void k_zero() {
    if (threadIdx.x < 65) g_mom[threadIdx.x] = 0.0;
}

__device__ __forceinline__ float wredsum(float v) {
#pragma unroll
    for (int o = 16; o; o >>= 1) v += __shfl_xor_sync(0xffffffffu, v, o);
    return v;
}
__device__ __forceinline__ float wredmax(float v) {
#pragma unroll
    for (int o = 16; o; o >>= 1) v = fmaxf(v, __shfl_xor_sync(0xffffffffu, v, o));
    return v;
}
__device__ __forceinline__ float wredmin(float v) {
#pragma unroll
    for (int o = 16; o; o >>= 1) v = fminf(v, __shfl_xor_sync(0xffffffffu, v, o));
    return v;
}

// ---------------- pass 1: attention + moment accumulation ----------------
__global__ __launch_bounds__(256) void k_pass1(
    const float4* __restrict__ feat, const int* __restrict__ npts,
    const int4*  __restrict__ coors,
    const float* __restrict__ wq, const float* __restrict__ wk,
    const float* __restrict__ wv, const float* __restrict__ wo,
    const float* __restrict__ bq, const float* __restrict__ bk,
    const float* __restrict__ bv, const float* __restrict__ bo)
{
    __shared__ float kvs[8][32][8];   // per point: k0,k1,k2,v0,v1,v2,pad,pad
    __shared__ float red[8][65];
    const int wl = threadIdx.x >> 5;
    const int lane = threadIdx.x & 31;
    const int n = blockIdx.x * 8 + wl;

    {
        float4 f = feat[n * MPTS + lane];
        const float x = f.x, y = f.y, z = f.z, I = f.w;

        float q0 = fmaf(x, wq[0], fmaf(y, wq[3], fmaf(z, wq[6], bq[0])));
        float q1 = fmaf(x, wq[1], fmaf(y, wq[4], fmaf(z, wq[7], bq[1])));
        float q2 = fmaf(x, wq[2], fmaf(y, wq[5], fmaf(z, wq[8], bq[2])));
        float k0 = fmaf(x, wk[0], fmaf(y, wk[3], fmaf(z, wk[6], bk[0])));
        float k1 = fmaf(x, wk[1], fmaf(y, wk[4], fmaf(z, wk[7], bk[1])));
        float k2 = fmaf(x, wk[2], fmaf(y, wk[5], fmaf(z, wk[8], bk[2])));
        float v0 = fmaf(x, wv[0], fmaf(y, wv[3], fmaf(z, wv[6], bv[0])));
        float v1 = fmaf(x, wv[1], fmaf(y, wv[4], fmaf(z, wv[7], bv[1])));
        float v2 = fmaf(x, wv[2], fmaf(y, wv[5], fmaf(z, wv[8], bv[2])));

        float* kp = kvs[wl][lane];
        *(float4*)kp       = make_float4(k0, k1, k2, v0);
        *(float2*)(kp + 4) = make_float2(v1, v2);
        __syncwarp();

        float n0 = 0.f, n1 = 0.f, n2 = 0.f, d0 = 0.f, d1 = 0.f, d2 = 0.f;
#pragma unroll
        for (int j = 0; j < 32; j++) {
            const float* kj = kvs[wl][j];
            float4 a = *(const float4*)kj;
            float2 b = *(const float2*)(kj + 4);
            float e0 = __expf(q0 * a.x);
            float e1 = __expf(q1 * a.y);
            float e2 = __expf(q2 * a.z);
            n0 = fmaf(e0, a.w, n0); d0 += e0;
            n1 = fmaf(e1, b.x, n1); d1 += e1;
            n2 = fmaf(e2, b.y, n2); d2 += e2;
        }
        float o0 = __fdividef(n0, d0);
        float o1 = __fdividef(n1, d1);
        float o2 = __fdividef(n2, d2);

        float a0 = fmaf(o0, wo[0], fmaf(o1, wo[3], fmaf(o2, wo[6], bo[0])));
        float a1 = fmaf(o0, wo[1], fmaf(o1, wo[4], fmaf(o2, wo[7], bo[1])));
        float a2 = fmaf(o0, wo[2], fmaf(o1, wo[5], fmaf(o2, wo[8], bo[2])));
        float matt = fmaxf(a0, fmaxf(a1, a2));

        float ssum = wredsum(matt);
        float wgt = matt / ssum;        // IEEE div: ssum may involve cancellation
        g_w[n * MPTS + lane] = wgt;

        const int m = npts[n];
        float sx = wredsum(x), sy = wredsum(y), sz = wredsum(z);
        float inv_m = 1.0f / (float)m;
        float mx = sx * inv_m, my = sy * inv_m, mz = sz * inv_m;

        const bool act = lane < m;
        float wmx = wredmax(act ? -FLT_MAX : wgt);
        float wmn = wredmin(act ?  FLT_MAX : wgt);

        float px = act ? x : 0.f, py = act ? y : 0.f;
        float pz = act ? z : 0.f, pI = act ? I : 0.f;
        float v14[14] = { px*px, px*py, px*pz, px*pI, py*py, py*pz, py*pI,
                          pz*pz, pz*pI, pI*pI, px, py, pz, pI };
#pragma unroll
        for (int t = 0; t < 14; t++) v14[t] = wredsum(v14[t]);

        if (lane == 0) {
            g_pmean[n] = make_float4(mx, my, mz, 0.f);
            g_wmm[n]   = make_float2(wmx, wmn);
            int4 cc = coors[n];
            float q6[6] = { (float)cc.w * 0.2f + 0.1f,
                            (float)cc.z * 0.2f - 39.9f,
                            (float)cc.y * 4.0f - 1.0f,
                            mx, my, mz };
            float fm = (float)m;
            float* r = red[wl];
#pragma unroll
            for (int t = 0; t < 14; t++) r[t] = v14[t];    // 0..9 PP, 10..13 Sv
            int idx = 14;
#pragma unroll
            for (int a = 0; a < 6; a++)
#pragma unroll
                for (int d = 0; d < 4; d++) r[idx++] = q6[a] * v14[10 + d];  // QS
#pragma unroll
            for (int a = 0; a < 6; a++)
#pragma unroll
                for (int b = a; b < 6; b++) r[idx++] = fm * q6[a] * q6[b];   // QQ
#pragma unroll
            for (int a = 0; a < 6; a++) r[idx++] = fm * q6[a];               // Qv
        }
    }
    __syncthreads();
    if (threadIdx.x < 65) {
        double acc = 0.0;
#pragma unroll
        for (int w2 = 0; w2 < 8; w2++) acc += (double)red[w2][threadIdx.x];
        atomicAdd(&g_mom[threadIdx.x], acc);
    }
}

// ---------------- stats: fold BN into per-channel coefficients ----------------
__global__ void k_stats(const float* __restrict__ pfn_w,
                        const float* __restrict__ gamma,
                        const float* __restrict__ beta)
{
    int c = threadIdx.x;
    if (c >= 64) return;
    float W[10];
#pragma unroll
    for (int r = 0; r < 10; r++) W[r] = pfn_w[r * 64 + c];
    float A[4] = { W[0]+W[4]+W[7], W[1]+W[5]+W[8], W[2]+W[6]+W[9], W[3] };
    float G[6] = { -(W[0]+W[7]), -(W[1]+W[8]), -(W[2]+W[9]), -W[4], -W[5], -W[6] };

    double mom[65];
    for (int t = 0; t < 65; t++) mom[t] = g_mom[t];

    double S1 = 0.0;
#pragma unroll
    for (int d = 0; d < 4; d++) S1 += mom[10 + d] * (double)A[d];
#pragma unroll
    for (int a = 0; a < 6; a++) S1 += mom[59 + a] * (double)G[a];
    double mean = S1 / NMTOT;

    double E2 = 0.0;
    int pi = 0;
#pragma unroll
    for (int d = 0; d < 4; d++)
#pragma unroll
        for (int e = d; e < 4; e++)
            E2 += (d == e ? 1.0 : 2.0) * (double)A[d] * (double)A[e] * mom[pi++];
#pragma unroll
    for (int a = 0; a < 6; a++)
#pragma unroll
        for (int d = 0; d < 4; d++)
            E2 += 2.0 * (double)G[a] * (double)A[d] * mom[14 + a * 4 + d];
    int qi = 38;
#pragma unroll
    for (int a = 0; a < 6; a++)
#pragma unroll
        for (int b = a; b < 6; b++)
            E2 += (a == b ? 1.0 : 2.0) * (double)G[a] * (double)G[b] * mom[qi++];
    E2 /= NMTOT;

    double var = E2 - mean * mean;
    float s = gamma[c] * (float)(1.0 / sqrt(var + 1e-3));
    float t = beta[c] - (float)mean * s;
#pragma unroll
    for (int d = 0; d < 4; d++) g_As[c * 4 + d] = A[d] * s;
#pragma unroll
    for (int a = 0; a < 6; a++) g_Gs[c * 6 + a] = G[a] * s;
    g_t[c] = t;
}

// ---------------- pass 2: fused PFN + BN + leaky + fa/fm maxes ----------------
__global__ __launch_bounds__(256) void k_pass2(
    const float4* __restrict__ feat, const int* __restrict__ npts,
    const int4*  __restrict__ coors, float* __restrict__ out)
{
    __shared__ float4 sp[8][32];
    __shared__ float  sw[8][32];
    const int lane = threadIdx.x & 31;
    const int wl = threadIdx.x >> 5;
    const int wg = (blockIdx.x * blockDim.x + threadIdx.x) >> 5;
    const int nwarps = (gridDim.x * blockDim.x) >> 5;

    float As0[4], As1[4], Gs0[6], Gs1[6];
#pragma unroll
    for (int d = 0; d < 4; d++) { As0[d] = g_As[lane*4+d]; As1[d] = g_As[(lane+32)*4+d]; }
#pragma unroll
    for (int a = 0; a < 6; a++) { Gs0[a] = g_Gs[lane*6+a]; Gs1[a] = g_Gs[(lane+32)*6+a]; }
    const float t0 = g_t[lane], t1 = g_t[lane + 32];
    const float tp0 = fmaxf(t0, 0.01f * t0);
    const float tp1 = fmaxf(t1, 0.01f * t1);

    for (int n = wg; n < NPIL; n += nwarps) {
        sp[wl][lane] = feat[n * MPTS + lane];
        sw[wl][lane] = g_w[n * MPTS + lane];
        const int m = npts[n];
        int4 cc = coors[n];
        float4 pm = g_pmean[n];
        float q6[6] = { (float)cc.w * 0.2f + 0.1f,
                        (float)cc.z * 0.2f - 39.9f,
                        (float)cc.y * 4.0f - 1.0f,
                        pm.x, pm.y, pm.z };
        float k0 = t0, k1 = t1;
#pragma unroll
        for (int a = 0; a < 6; a++) {
            k0 = fmaf(q6[a], Gs0[a], k0);
            k1 = fmaf(q6[a], Gs1[a], k1);
        }
        float fm0, fm1, fa0, fa1;
        if (m < MPTS) {           // masked rows: x = t_c uniformly, closed form
            float2 wmm = g_wmm[n];
            fm0 = tp0; fm1 = tp1;
            fa0 = (tp0 >= 0.f) ? tp0 * wmm.x : tp0 * wmm.y;
            fa1 = (tp1 >= 0.f) ? tp1 * wmm.x : tp1 * wmm.y;
        } else {
            fm0 = fm1 = fa0 = fa1 = -FLT_MAX;
        }
        __syncwarp();
        for (int i = 0; i < m; i++) {
            float4 p = sp[wl][i];
            float wi = sw[wl][i];
            float u0 = fmaf(p.x, As0[0], fmaf(p.y, As0[1],
                       fmaf(p.z, As0[2], fmaf(p.w, As0[3], k0))));
            u0 = fmaxf(u0, 0.01f * u0);
            fm0 = fmaxf(fm0, u0);
            fa0 = fmaxf(fa0, wi * u0);
            float u1 = fmaf(p.x, As1[0], fmaf(p.y, As1[1],
                       fmaf(p.z, As1[2], fmaf(p.w, As1[3], k1))));
            u1 = fmaxf(u1, 0.01f * u1);
            fm1 = fmaxf(fm1, u1);
            fa1 = fmaxf(fa1, wi * u1);
        }
        out[n * 64 + lane]      = 0.5f * (fa0 + fm0);
        out[n * 64 + lane + 32] = 0.5f * (fa1 + fm1);
        __syncwarp();
    }
}

// ---------------- launch ----------------
extern "C" void kernel_launch(void* const* d_in, const int* in_sizes, int n_in,
                              void* d_out, int out_size)
{
    const float4* feat  = (const float4*)d_in[0];
    const int*    npts  = (const int*)  d_in[1];
    const int4*   coors = (const int4*) d_in[2];
    const float*  pfn_w = (const float*)d_in[3];
    const float*  gamma = (const float*)d_in[4];
    const float*  beta  = (const float*)d_in[5];
    const float*  wq    = (const float*)d_in[6];
    const float*  wk    = (const float*)d_in[7];
    const float*  wv    = (const float*)d_in[8];
    const float*  wo    = (const float*)d_in[9];
    const float*  bq    = (const float*)d_in[10];
    const float*  bk    = (const float*)d_in[11];
    const float*  bv    = (const float*)d_in[12];
    const float*  bo    = (const float*)d_in[13];
    float* out = (float*)d_out;

    k_zero<<<1, 65>>>();
    k_pass1<<<(NPIL + 7) / 8, 256>>>(feat, npts, coors, wq, wk, wv, wo, bq, bk, bv, bo);
    k_stats<<<1, 64>>>(pfn_w, gamma, beta);
    k_pass2<<<592, 256>>>(feat, npts, coors, out);
}